// round 2
// baseline (speedup 1.0000x reference)
#include <cuda_runtime.h>

#define TPB 256
#define R 32
#define STR 34

typedef unsigned long long ull;

static __device__ __forceinline__ ull pk(float lo, float hi){ ull r; asm("mov.b64 %0,{%1,%2};":"=l"(r):"f"(lo),"f"(hi)); return r; }
static __device__ __forceinline__ void upk(ull v, float &lo, float &hi){ asm("mov.b64 {%0,%1},%2;":"=f"(lo),"=f"(hi):"l"(v)); }
static __device__ __forceinline__ void fma2(ull &d, ull a, ull b){ asm("fma.rn.f32x2 %0,%1,%2,%0;":"+l"(d):"l"(a),"l"(b)); }
static __device__ __forceinline__ float siluf(float z){ return z*(1.f/(1.f+__expf(-z))); }
static __device__ __forceinline__ float dsiluf(float z){ float s=1.f/(1.f+__expf(-z)); return s*(1.f+z*(1.f-s)); }

__device__ float g_cd[2][256];

// SMEM offsets in floats (buffers are [col][row] with row stride STR=34)
#define OFF_BASE 0
#define OFF_TZ1  8704
#define OFF_A1   17408
#define OFF_A2   26112
#define OFF_TA1  34816
#define OFF_TA2  43520
#define OFF_EPS  52224
#define OFF_CU   54400
#define OFF_CV   54944
#define OFF_CF   55488
#define OFF_DR   56032
#define SMEM_FLOATS 56064

__global__ void precompute_k(const float* __restrict__ cu, const float* __restrict__ cv,
                             const float* __restrict__ W1){
    int c = threadIdx.x;
    float su = 0.f, sv = 0.f;
    #pragma unroll
    for (int j = 0; j < 16; j++){
        float w = __ldg(W1 + (65+j)*256 + c);
        su += __ldg(cu + j) * w;
        sv += __ldg(cv + j) * w;
    }
    g_cd[0][c] = su;
    g_cd[1][c] = sv;
}

// GEMM: acts in SMEM [k][row] (broadcast reads, row-pair packed), weights streamed via LDG.128.
// Thread computes 4 cols x (2*RP) rows. aP[rp][ci] packs rows (r0+2rp, r0+2rp+1) of col c0+ci.
template<int K, int LDW, int RP, bool DUAL>
static __device__ __forceinline__ void gemm(const float* sA, const float* sT,
    const float* __restrict__ W, int c0, int r0, ull (&aP)[RP][4], ull (&aT)[RP][4])
{
    #pragma unroll
    for (int i = 0; i < RP; i++){
        #pragma unroll
        for (int j = 0; j < 4; j++){ aP[i][j] = 0ULL; if (DUAL) aT[i][j] = 0ULL; }
    }
    #pragma unroll 4
    for (int k = 0; k < K; k++){
        float4 w = __ldg(reinterpret_cast<const float4*>(W + k*LDW + c0));
        ull w0 = pk(w.x, w.x), w1 = pk(w.y, w.y), w2 = pk(w.z, w.z), w3 = pk(w.w, w.w);
        const float* ap = sA + k*STR + r0;
        #pragma unroll
        for (int rp = 0; rp < RP; rp++){
            ull a2 = *reinterpret_cast<const ull*>(ap + 2*rp);
            fma2(aP[rp][0], a2, w0); fma2(aP[rp][1], a2, w1);
            fma2(aP[rp][2], a2, w2); fma2(aP[rp][3], a2, w3);
        }
        if (DUAL){
            const float* tp = sT + k*STR + r0;
            #pragma unroll
            for (int rp = 0; rp < RP; rp++){
                ull a2 = *reinterpret_cast<const ull*>(tp + 2*rp);
                fma2(aT[rp][0], a2, w0); fma2(aT[rp][1], a2, w1);
                fma2(aT[rp][2], a2, w2); fma2(aT[rp][3], a2, w3);
            }
        }
    }
}

__global__ void __launch_bounds__(TPB, 1) node_main(
    const float* __restrict__ gt, const float* __restrict__ gx, const float* __restrict__ geps,
    const float* __restrict__ gcu, const float* __restrict__ gcv, const float* __restrict__ gcf,
    const float* __restrict__ W1, const float* __restrict__ b1,
    const float* __restrict__ W2, const float* __restrict__ b2,
    const float* __restrict__ W3, const float* __restrict__ b3,
    float* __restrict__ out, int B)
{
    extern __shared__ float sm[];
    const int tid  = threadIdx.x;
    const int row0 = blockIdx.x * R;

    float* BASE = sm + OFF_BASE;   // y@W1y + t*W1t + b1     [256][R]
    float* TZ1  = sm + OFF_TZ1;    // e@W1y                  [256][R]
    float* A1   = sm + OFF_A1;     // layer1 acts            [256][R]
    float* A2   = sm + OFF_A2;     // layer2 acts            [256][R]
    float* TA1  = sm + OFF_TA1;    // tangent l1 acts        [256][R]
    float* TA2  = sm + OFF_TA2;    // tangent l2 acts        [256][R]
    float* EPS  = sm + OFF_EPS;    // eps transposed         [64][R]
    float* CUt  = sm + OFF_CU;     // cond tiles transposed  [16][R]
    float* CVt  = sm + OFF_CV;
    float* CFt  = sm + OFF_CF;
    float* DR   = sm + OFF_DR;     // per-row divergence acc [R]
    float* YSH  = A2;              // overlay: y transposed (used only before first layer2)
    float* OUT3 = TA1;             // overlay: layer3 full output [128][R]
    float* FT   = TA2;             // overlay: ft staging        [64][R]
    float* PR   = A1;              // overlay: tangent-out * eps [64][R]

    // ---- P0: tile loads (transposed) ----
    for (int i = tid; i < 64*R; i += TPB){
        int r = i & 31, d = i >> 5; int gr = row0 + r;
        YSH[d*STR + r] = (gr < B) ? gx[(size_t)gr*65 + d]  : 0.f;
        EPS[d*STR + r] = (gr < B) ? geps[(size_t)gr*64 + d] : 0.f;
    }
    for (int i = tid; i < 16*R; i += TPB){
        int r = i & 31, j = i >> 5; int gr = row0 + r; int gi = (gr < B) ? gr : 0;
        CUt[j*STR + r] = gcu[(size_t)gi*16 + j];
        CVt[j*STR + r] = gcv[(size_t)gi*16 + j];
        CFt[j*STR + r] = gcf[(size_t)gi*16 + j];
    }
    if (tid < R) DR[tid] = 0.f;
    __syncthreads();

    // ---- P1: dual base GEMM: BASE = y@W1y (+t*W1t+b1), TZ1 = e@W1y ----
    {
        int cg = tid & 63, rg = tid >> 6; int c0 = 4*cg, r0 = 8*rg;
        ull aP[4][4], aT[4][4];
        gemm<64,256,4,true>(YSH, EPS, W1, c0, r0, aP, aT);
        float tv = __ldg(gt);
        #pragma unroll
        for (int ci = 0; ci < 4; ci++){
            int c = c0 + ci;
            float s = tv*__ldg(W1 + 64*256 + c) + __ldg(b1 + c);
            #pragma unroll
            for (int rp = 0; rp < 4; rp++){
                float lo, hi;
                upk(aP[rp][ci], lo, hi);
                *reinterpret_cast<float2*>(BASE + c*STR + r0 + 2*rp) = make_float2(lo+s, hi+s);
                upk(aT[rp][ci], lo, hi);
                *reinterpret_cast<float2*>(TZ1 + c*STR + r0 + 2*rp) = make_float2(lo, hi);
            }
        }
    }
    __syncthreads();

    // ---- helpers ----
    auto fillA1 = [&](const float* ct){  // A1 = silu(BASE + cond@W1c)
        int cg = tid & 63, rg = tid >> 6; int c0 = 4*cg, r0 = 8*rg;
        ull aP[4][4];
        gemm<16,256,4,false>(ct, ct, W1 + 65*256, c0, r0, aP, aP);
        #pragma unroll
        for (int ci = 0; ci < 4; ci++){ int c = c0 + ci;
            #pragma unroll
            for (int rp = 0; rp < 4; rp++){
                float lo, hi; upk(aP[rp][ci], lo, hi);
                float2 b = *reinterpret_cast<const float2*>(BASE + c*STR + r0 + 2*rp);
                *reinterpret_cast<float2*>(A1 + c*STR + r0 + 2*rp) =
                    make_float2(siluf(b.x + lo), siluf(b.y + hi));
            }
        }
    };
    auto layer2s = [&](){                // A2 = silu(A1@W2 + b2)
        int cg = tid & 63, rg = tid >> 6; int c0 = 4*cg, r0 = 8*rg;
        ull aP[4][4];
        gemm<256,256,4,false>(A1, A1, W2, c0, r0, aP, aP);
        #pragma unroll
        for (int ci = 0; ci < 4; ci++){ int c = c0 + ci; float bb = __ldg(b2 + c);
            #pragma unroll
            for (int rp = 0; rp < 4; rp++){
                float lo, hi; upk(aP[rp][ci], lo, hi);
                *reinterpret_cast<float2*>(A2 + c*STR + r0 + 2*rp) =
                    make_float2(siluf(lo + bb), siluf(hi + bb));
            }
        }
    };
    auto layer3full = [&](){             // OUT3 = A2@W3 + b3 (all 128 cols)
        int cg = tid & 31, rg = tid >> 5; int c0 = 4*cg, r0 = 4*rg;
        ull aP[2][4];
        gemm<256,128,2,false>(A2, A2, W3, c0, r0, aP, aP);
        #pragma unroll
        for (int ci = 0; ci < 4; ci++){ int c = c0 + ci; float bb = __ldg(b3 + c);
            #pragma unroll
            for (int rp = 0; rp < 2; rp++){
                float lo, hi; upk(aP[rp][ci], lo, hi);
                *reinterpret_cast<float2*>(OUT3 + c*STR + r0 + 2*rp) = make_float2(lo+bb, hi+bb);
            }
        }
    };
    auto fillJ = [&](int uv){            // A1 = silu(BASE+cd), TA1 = silu'(z)*TZ1
        int cg = tid & 63, rg = tid >> 6; int c0 = 4*cg, r0 = 8*rg;
        #pragma unroll
        for (int ci = 0; ci < 4; ci++){ int c = c0 + ci;
            float cd = g_cd[uv][c];
            #pragma unroll
            for (int rp = 0; rp < 4; rp++){
                float2 b  = *reinterpret_cast<const float2*>(BASE + c*STR + r0 + 2*rp);
                float2 tz = *reinterpret_cast<const float2*>(TZ1  + c*STR + r0 + 2*rp);
                float z0 = b.x + cd, z1 = b.y + cd;
                *reinterpret_cast<float2*>(A1  + c*STR + r0 + 2*rp) = make_float2(siluf(z0), siluf(z1));
                *reinterpret_cast<float2*>(TA1 + c*STR + r0 + 2*rp) =
                    make_float2(dsiluf(z0)*tz.x, dsiluf(z1)*tz.y);
            }
        }
    };
    auto layer2d = [&](){                // dual: A2 = silu(z2), TA2 = silu'(z2)*tz2
        int cg = tid & 63, rg = tid >> 6; int c0 = 4*cg, r0 = 8*rg;
        ull aP[4][4], aT[4][4];
        gemm<256,256,4,true>(A1, TA1, W2, c0, r0, aP, aT);
        #pragma unroll
        for (int ci = 0; ci < 4; ci++){ int c = c0 + ci; float bb = __ldg(b2 + c);
            #pragma unroll
            for (int rp = 0; rp < 4; rp++){
                float z0, z1, t0, t1;
                upk(aP[rp][ci], z0, z1); upk(aT[rp][ci], t0, t1);
                z0 += bb; z1 += bb;
                *reinterpret_cast<float2*>(A2  + c*STR + r0 + 2*rp) = make_float2(siluf(z0), siluf(z1));
                *reinterpret_cast<float2*>(TA2 + c*STR + r0 + 2*rp) =
                    make_float2(dsiluf(z0)*t0, dsiluf(z1)*t1);
            }
        }
    };
    auto tl3 = [&](){                    // PR = (TA2@W3[:, :64]) * eps
        int cg = tid & 15, rg = tid >> 4; int c0 = 4*cg, r0 = 2*rg;
        ull aP[1][4];
        gemm<256,128,1,false>(TA2, TA2, W3, c0, r0, aP, aP);
        #pragma unroll
        for (int ci = 0; ci < 4; ci++){ int c = c0 + ci;
            float lo, hi; upk(aP[0][ci], lo, hi);
            float2 e = *reinterpret_cast<const float2*>(EPS + c*STR + r0);
            *reinterpret_cast<float2*>(PR + c*STR + r0) = make_float2(lo*e.x, hi*e.y);
        }
    };
    auto reduce_corr = [&](float sgn){   // += sgn * sum_c (FT-OUT3_lo)*OUT3_hi
        if (tid < R){
            float s = 0.f;
            for (int c = 0; c < 64; c++){
                float d = FT[c*STR + tid] - OUT3[c*STR + tid];
                s += d * OUT3[(64+c)*STR + tid];
            }
            DR[tid] += sgn * s;
        }
    };
    auto reduce_div = [&](float sgn){
        if (tid < R){
            float s = 0.f;
            for (int c = 0; c < 64; c++) s += PR[c*STR + tid];
            DR[tid] += sgn * s;
        }
    };

    // ---- pass f (vector-field cols only; stage FT, write ft to gmem) ----
    fillA1(CFt); __syncthreads();
    layer2s();   __syncthreads();
    {
        int cg = tid & 15, rg = tid >> 4; int c0 = 4*cg, r0 = 2*rg;
        ull aP[1][4];
        gemm<256,128,1,false>(A2, A2, W3, c0, r0, aP, aP);
        #pragma unroll
        for (int ci = 0; ci < 4; ci++){ int c = c0 + ci; float bb = __ldg(b3 + c);
            float lo, hi; upk(aP[0][ci], lo, hi);
            lo += bb; hi += bb;
            *reinterpret_cast<float2*>(FT + c*STR + r0) = make_float2(lo, hi);
            int gr = row0 + r0;
            if (gr   < B) out[(size_t)gr*65 + c]     = lo;
            if (gr+1 < B) out[(size_t)(gr+1)*65 + c] = hi;
        }
    }
    __syncthreads();

    // ---- pass u: corr_u = sum (ft-ut)*score_u ----
    fillA1(CUt); __syncthreads();
    layer2s();   __syncthreads();
    layer3full(); __syncthreads();
    reduce_corr(1.f); __syncthreads();

    // ---- pass v: corr_v = sum (vt-ft)*score_v ----
    fillA1(CVt); __syncthreads();
    layer2s();   __syncthreads();
    layer3full(); __syncthreads();
    reduce_corr(-1.f); __syncthreads();

    // ---- JVP through u-model (fixed cond_u[0]): div -= e.(Ju e) ----
    fillJ(0);  __syncthreads();
    layer2d(); __syncthreads();
    tl3();     __syncthreads();
    reduce_div(-1.f); __syncthreads();

    // ---- JVP through v-model (fixed cond_v[0]): div += e.(Jv e) ----
    fillJ(1);  __syncthreads();
    layer2d(); __syncthreads();
    tl3();     __syncthreads();
    reduce_div(1.f); __syncthreads();

    // ---- write dr ----
    if (tid < R){
        int gr = row0 + tid;
        if (gr < B) out[(size_t)gr*65 + 64] = DR[tid];
    }
}

extern "C" void kernel_launch(void* const* d_in, const int* in_sizes, int n_in,
                              void* d_out, int out_size)
{
    const float* gt  = (const float*)d_in[0];
    const float* gx  = (const float*)d_in[1];
    const float* ge  = (const float*)d_in[2];
    const float* gcu = (const float*)d_in[3];
    const float* gcv = (const float*)d_in[4];
    const float* gcf = (const float*)d_in[5];
    const float* W1  = (const float*)d_in[6];
    const float* b1  = (const float*)d_in[7];
    const float* W2  = (const float*)d_in[8];
    const float* b2  = (const float*)d_in[9];
    const float* W3  = (const float*)d_in[10];
    const float* b3  = (const float*)d_in[11];
    float* out = (float*)d_out;

    int B = in_sizes[1] / 65;
    int grid = (B + R - 1) / R;

    cudaFuncSetAttribute(node_main, cudaFuncAttributeMaxDynamicSharedMemorySize, SMEM_FLOATS*4);

    precompute_k<<<1, 256>>>(gcu, gcv, W1);
    node_main<<<grid, TPB, SMEM_FLOATS*4>>>(gt, gx, ge, gcu, gcv, gcf,
                                            W1, b1, W2, b2, W3, b3, out, B);
}

// round 4
// speedup vs baseline: 1.1021x; 1.1021x over previous
#include <cuda_runtime.h>

#define TPB 512
#define R 32
#define STR 34

typedef unsigned long long ull;

static __device__ __forceinline__ ull pk(float lo, float hi){ ull r; asm("mov.b64 %0,{%1,%2};":"=l"(r):"f"(lo),"f"(hi)); return r; }
static __device__ __forceinline__ void upk(ull v, float &lo, float &hi){ asm("mov.b64 {%0,%1},%2;":"=f"(lo),"=f"(hi):"l"(v)); }
static __device__ __forceinline__ void fma2(ull &d, ull a, ull b){ asm("fma.rn.f32x2 %0,%1,%2,%0;":"+l"(d):"l"(a),"l"(b)); }
static __device__ __forceinline__ float siluf(float z){ return z*(1.f/(1.f+__expf(-z))); }
static __device__ __forceinline__ float dsiluf(float z){ float s=1.f/(1.f+__expf(-z)); return s*(1.f+z*(1.f-s)); }

__device__ float g_cd[2][256];

// SMEM offsets in floats (buffers are [col][row] with row stride STR=34)
#define OFF_BASE 0
#define OFF_TZ1  8704
#define OFF_A1   17408
#define OFF_A2   26112
#define OFF_TA1  34816
#define OFF_TA2  43520
#define OFF_EPS  52224
#define OFF_CU   54400
#define OFF_CV   54944
#define OFF_CF   55488
#define OFF_DR   56032
#define SMEM_FLOATS 56064

__global__ void precompute_k(const float* __restrict__ cu, const float* __restrict__ cv,
                             const float* __restrict__ W1){
    int c = threadIdx.x;
    float su = 0.f, sv = 0.f;
    #pragma unroll
    for (int j = 0; j < 16; j++){
        float w = __ldg(W1 + (65+j)*256 + c);
        su += __ldg(cu + j) * w;
        sv += __ldg(cv + j) * w;
    }
    g_cd[0][c] = su;
    g_cd[1][c] = sv;
}

// GEMM: acts in SMEM [k][row] (row-pair packed), weights streamed via LDG.
// Thread computes CW cols x (2*RP) rows.
template<int K, int LDW, int RP, int CW, bool DUAL>
static __device__ __forceinline__ void gemm(const float* sA, const float* sT,
    const float* __restrict__ W, int c0, int r0, ull (&aP)[RP][CW], ull (&aT)[RP][CW])
{
    #pragma unroll
    for (int i = 0; i < RP; i++){
        #pragma unroll
        for (int j = 0; j < CW; j++){ aP[i][j] = 0ULL; if (DUAL) aT[i][j] = 0ULL; }
    }
    #pragma unroll 4
    for (int k = 0; k < K; k++){
        ull wv[CW];
        if (CW == 4){
            float4 w = __ldg(reinterpret_cast<const float4*>(W + k*LDW + c0));
            wv[0] = pk(w.x, w.x); wv[1] = pk(w.y, w.y);
            wv[2] = pk(w.z, w.z); wv[3] = pk(w.w, w.w);
        } else {
            float2 w = __ldg(reinterpret_cast<const float2*>(W + k*LDW + c0));
            wv[0] = pk(w.x, w.x); wv[1] = pk(w.y, w.y);
        }
        const float* ap = sA + k*STR + r0;
        #pragma unroll
        for (int rp = 0; rp < RP; rp++){
            ull a2 = *reinterpret_cast<const ull*>(ap + 2*rp);
            #pragma unroll
            for (int ci = 0; ci < CW; ci++) fma2(aP[rp][ci], a2, wv[ci]);
        }
        if (DUAL){
            const float* tp = sT + k*STR + r0;
            #pragma unroll
            for (int rp = 0; rp < RP; rp++){
                ull a2 = *reinterpret_cast<const ull*>(tp + 2*rp);
                #pragma unroll
                for (int ci = 0; ci < CW; ci++) fma2(aT[rp][ci], a2, wv[ci]);
            }
        }
    }
}

__global__ void __launch_bounds__(TPB, 1) node_main(
    const float* __restrict__ gt, const float* __restrict__ gx, const float* __restrict__ geps,
    const float* __restrict__ gcu, const float* __restrict__ gcv, const float* __restrict__ gcf,
    const float* __restrict__ W1, const float* __restrict__ b1,
    const float* __restrict__ W2, const float* __restrict__ b2,
    const float* __restrict__ W3, const float* __restrict__ b3,
    float* __restrict__ out, int B)
{
    extern __shared__ float sm[];
    const int tid  = threadIdx.x;
    const int row0 = blockIdx.x * R;

    float* BASE = sm + OFF_BASE;   // y@W1y + t*W1t + b1     [256][R]
    float* TZ1  = sm + OFF_TZ1;    // e@W1y                  [256][R]
    float* A1   = sm + OFF_A1;     // layer1 acts            [256][R]
    float* A2   = sm + OFF_A2;     // layer2 acts            [256][R]
    float* TA1  = sm + OFF_TA1;    // tangent l1 acts        [256][R]
    float* TA2  = sm + OFF_TA2;    // tangent l2 acts        [256][R]
    float* EPS  = sm + OFF_EPS;    // eps transposed         [64][R]
    float* CUt  = sm + OFF_CU;     // cond tiles transposed  [16][R]
    float* CVt  = sm + OFF_CV;
    float* CFt  = sm + OFF_CF;
    float* DR   = sm + OFF_DR;     // per-row divergence acc [R]
    float* YSH  = A2;              // overlay: y transposed (used only before first layer2)
    float* OUT3 = TA1;             // overlay: layer3 full output [128][R]
    float* FT   = TA2;             // overlay: ft staging        [64][R]
    float* PR   = A1;              // overlay: tangent-out * eps [64][R]

    // ---- P0: tile loads (transposed) ----
    for (int i = tid; i < 64*R; i += TPB){
        int r = i & 31, d = i >> 5; int gr = row0 + r;
        YSH[d*STR + r] = (gr < B) ? gx[(size_t)gr*65 + d]  : 0.f;
        EPS[d*STR + r] = (gr < B) ? geps[(size_t)gr*64 + d] : 0.f;
    }
    for (int i = tid; i < 16*R; i += TPB){
        int r = i & 31, j = i >> 5; int gr = row0 + r; int gi = (gr < B) ? gr : 0;
        CUt[j*STR + r] = gcu[(size_t)gi*16 + j];
        CVt[j*STR + r] = gcv[(size_t)gi*16 + j];
        CFt[j*STR + r] = gcf[(size_t)gi*16 + j];
    }
    if (tid < R) DR[tid] = 0.f;
    __syncthreads();

    // Thread mappings:
    //  256-col GEMMs: 64 colgroups x 8 rowgroups, tile 4 cols x 4 rows (RP=2)
    const int cgA = tid & 63, rgA = tid >> 6;
    const int c0A = 4*cgA,    r0A = 4*rgA;
    //  128-col layer3: 32 colgroups x 16 rowgroups, tile 4 cols x 2 rows (RP=1)
    const int cg3 = tid & 31, rg3 = tid >> 5;
    const int c03 = 4*cg3,    r03 = 2*rg3;
    //  64-col tangent layer3: 32 colgroups(2-wide) x 16 rowgroups, RP=1
    const int c0T = 2*(tid & 31), r0T = 2*(tid >> 5);
    //  reductions: 16 threads per row (4 cols each of 64), row = tid>>4
    const int rRed = tid >> 4, cRed = 4*(tid & 15);

    // ---- P1: dual base GEMM: BASE = y@W1y (+t*W1t+b1), TZ1 = e@W1y ----
    {
        ull aP[2][4], aT[2][4];
        gemm<64,256,2,4,true>(YSH, EPS, W1, c0A, r0A, aP, aT);
        float tv = __ldg(gt);
        #pragma unroll
        for (int ci = 0; ci < 4; ci++){
            int c = c0A + ci;
            float s = tv*__ldg(W1 + 64*256 + c) + __ldg(b1 + c);
            #pragma unroll
            for (int rp = 0; rp < 2; rp++){
                float lo, hi;
                upk(aP[rp][ci], lo, hi);
                *reinterpret_cast<float2*>(BASE + c*STR + r0A + 2*rp) = make_float2(lo+s, hi+s);
                upk(aT[rp][ci], lo, hi);
                *reinterpret_cast<float2*>(TZ1 + c*STR + r0A + 2*rp) = make_float2(lo, hi);
            }
        }
    }
    __syncthreads();

    // ---- helpers ----
    auto fillA1 = [&](const float* ct){  // A1 = silu(BASE + cond@W1c)
        ull aP[2][4];
        gemm<16,256,2,4,false>(ct, ct, W1 + 65*256, c0A, r0A, aP, aP);
        #pragma unroll
        for (int ci = 0; ci < 4; ci++){ int c = c0A + ci;
            #pragma unroll
            for (int rp = 0; rp < 2; rp++){
                float lo, hi; upk(aP[rp][ci], lo, hi);
                float2 b = *reinterpret_cast<const float2*>(BASE + c*STR + r0A + 2*rp);
                *reinterpret_cast<float2*>(A1 + c*STR + r0A + 2*rp) =
                    make_float2(siluf(b.x + lo), siluf(b.y + hi));
            }
        }
    };
    auto layer2s = [&](){                // A2 = silu(A1@W2 + b2)
        ull aP[2][4];
        gemm<256,256,2,4,false>(A1, A1, W2, c0A, r0A, aP, aP);
        #pragma unroll
        for (int ci = 0; ci < 4; ci++){ int c = c0A + ci; float bb = __ldg(b2 + c);
            #pragma unroll
            for (int rp = 0; rp < 2; rp++){
                float lo, hi; upk(aP[rp][ci], lo, hi);
                *reinterpret_cast<float2*>(A2 + c*STR + r0A + 2*rp) =
                    make_float2(siluf(lo + bb), siluf(hi + bb));
            }
        }
    };
    auto layer3full = [&](bool writeFT){ // OUT3 = A2@W3 + b3 (128 cols); optionally stage FT+gmem
        ull aP[1][4];
        gemm<256,128,1,4,false>(A2, A2, W3, c03, r03, aP, aP);
        #pragma unroll
        for (int ci = 0; ci < 4; ci++){ int c = c03 + ci; float bb = __ldg(b3 + c);
            float lo, hi; upk(aP[0][ci], lo, hi);
            lo += bb; hi += bb;
            *reinterpret_cast<float2*>(OUT3 + c*STR + r03) = make_float2(lo, hi);
            if (writeFT && c < 64){
                *reinterpret_cast<float2*>(FT + c*STR + r03) = make_float2(lo, hi);
                int gr = row0 + r03;
                if (gr   < B) out[(size_t)gr*65 + c]     = lo;
                if (gr+1 < B) out[(size_t)(gr+1)*65 + c] = hi;
            }
        }
    };
    auto fillJ = [&](int uv){            // A1 = silu(BASE+cd), TA1 = silu'(z)*TZ1
        #pragma unroll
        for (int ci = 0; ci < 4; ci++){ int c = c0A + ci;
            float cd = g_cd[uv][c];
            #pragma unroll
            for (int rp = 0; rp < 2; rp++){
                float2 b  = *reinterpret_cast<const float2*>(BASE + c*STR + r0A + 2*rp);
                float2 tz = *reinterpret_cast<const float2*>(TZ1  + c*STR + r0A + 2*rp);
                float z0 = b.x + cd, z1 = b.y + cd;
                *reinterpret_cast<float2*>(A1  + c*STR + r0A + 2*rp) = make_float2(siluf(z0), siluf(z1));
                *reinterpret_cast<float2*>(TA1 + c*STR + r0A + 2*rp) =
                    make_float2(dsiluf(z0)*tz.x, dsiluf(z1)*tz.y);
            }
        }
    };
    auto layer2d = [&](){                // dual: A2 = silu(z2), TA2 = silu'(z2)*tz2
        ull aP[2][4], aT[2][4];
        gemm<256,256,2,4,true>(A1, TA1, W2, c0A, r0A, aP, aT);
        #pragma unroll
        for (int ci = 0; ci < 4; ci++){ int c = c0A + ci; float bb = __ldg(b2 + c);
            #pragma unroll
            for (int rp = 0; rp < 2; rp++){
                float z0, z1, t0, t1;
                upk(aP[rp][ci], z0, z1); upk(aT[rp][ci], t0, t1);
                z0 += bb; z1 += bb;
                *reinterpret_cast<float2*>(A2  + c*STR + r0A + 2*rp) = make_float2(siluf(z0), siluf(z1));
                *reinterpret_cast<float2*>(TA2 + c*STR + r0A + 2*rp) =
                    make_float2(dsiluf(z0)*t0, dsiluf(z1)*t1);
            }
        }
    };
    auto tl3 = [&](){                    // PR = (TA2@W3[:, :64]) * eps
        ull aP[1][2];
        gemm<256,128,1,2,false>(TA2, TA2, W3, c0T, r0T, aP, aP);
        #pragma unroll
        for (int ci = 0; ci < 2; ci++){ int c = c0T + ci;
            float lo, hi; upk(aP[0][ci], lo, hi);
            float2 e = *reinterpret_cast<const float2*>(EPS + c*STR + r0T);
            *reinterpret_cast<float2*>(PR + c*STR + r0T) = make_float2(lo*e.x, hi*e.y);
        }
    };
    // Parallel row reductions: 16 threads/row, each sums a 4-col strip, then a
    // 4-step shuffle tree folds the 16 partials; lane (tid&15)==0 accumulates.
    auto reduce_corr = [&](float sgn){   // DR[r] += sgn * sum_c (FT-OUT3_lo)*OUT3_hi
        float s = 0.f;
        #pragma unroll
        for (int j = 0; j < 4; j++){
            int c = cRed + j;
            float d = FT[c*STR + rRed] - OUT3[c*STR + rRed];
            s += d * OUT3[(64+c)*STR + rRed];
        }
        s += __shfl_down_sync(0xffffffffu, s, 8, 16);
        s += __shfl_down_sync(0xffffffffu, s, 4, 16);
        s += __shfl_down_sync(0xffffffffu, s, 2, 16);
        s += __shfl_down_sync(0xffffffffu, s, 1, 16);
        if ((tid & 15) == 0) DR[rRed] += sgn * s;
    };
    auto reduce_div = [&](float sgn){    // DR[r] += sgn * sum_c PR
        float s = 0.f;
        #pragma unroll
        for (int j = 0; j < 4; j++) s += PR[(cRed + j)*STR + rRed];
        s += __shfl_down_sync(0xffffffffu, s, 8, 16);
        s += __shfl_down_sync(0xffffffffu, s, 4, 16);
        s += __shfl_down_sync(0xffffffffu, s, 2, 16);
        s += __shfl_down_sync(0xffffffffu, s, 1, 16);
        if ((tid & 15) == 0) DR[rRed] += sgn * s;
    };

    // ---- pass f: stage FT + write ft ----
    fillA1(CFt); __syncthreads();
    layer2s();   __syncthreads();
    layer3full(true); __syncthreads();

    // ---- pass u: corr_u = sum (ft-ut)*score_u ----
    fillA1(CUt); __syncthreads();
    layer2s();   __syncthreads();
    layer3full(false); __syncthreads();
    reduce_corr(1.f); __syncthreads();

    // ---- pass v: corr_v = sum (vt-ft)*score_v ----
    fillA1(CVt); __syncthreads();
    layer2s();   __syncthreads();
    layer3full(false); __syncthreads();
    reduce_corr(-1.f); __syncthreads();

    // ---- JVP through u-model (fixed cond_u[0]): div -= e.(Ju e) ----
    fillJ(0);  __syncthreads();
    layer2d(); __syncthreads();
    tl3();     __syncthreads();
    reduce_div(-1.f); __syncthreads();

    // ---- JVP through v-model (fixed cond_v[0]): div += e.(Jv e) ----
    fillJ(1);  __syncthreads();
    layer2d(); __syncthreads();
    tl3();     __syncthreads();
    reduce_div(1.f); __syncthreads();

    // ---- write dr ----
    if (tid < R){
        int gr = row0 + tid;
        if (gr < B) out[(size_t)gr*65 + 64] = DR[tid];
    }
}

extern "C" void kernel_launch(void* const* d_in, const int* in_sizes, int n_in,
                              void* d_out, int out_size)
{
    const float* gt  = (const float*)d_in[0];
    const float* gx  = (const float*)d_in[1];
    const float* ge  = (const float*)d_in[2];
    const float* gcu = (const float*)d_in[3];
    const float* gcv = (const float*)d_in[4];
    const float* gcf = (const float*)d_in[5];
    const float* W1  = (const float*)d_in[6];
    const float* b1  = (const float*)d_in[7];
    const float* W2  = (const float*)d_in[8];
    const float* b2  = (const float*)d_in[9];
    const float* W3  = (const float*)d_in[10];
    const float* b3  = (const float*)d_in[11];
    float* out = (float*)d_out;

    int B = in_sizes[1] / 65;
    int grid = (B + R - 1) / R;

    cudaFuncSetAttribute(node_main, cudaFuncAttributeMaxDynamicSharedMemorySize, SMEM_FLOATS*4);

    precompute_k<<<1, 256>>>(gcu, gcv, W1);
    node_main<<<grid, TPB, SMEM_FLOATS*4>>>(gt, gx, ge, gcu, gcv, gcf,
                                            W1, b1, W2, b2, W3, b3, out, B);
}

// round 5
// speedup vs baseline: 1.4054x; 1.2752x over previous
#include <cuda_runtime.h>

#define TPB 512

typedef unsigned long long ull;

static __device__ __forceinline__ ull pk(float lo, float hi){ ull r; asm("mov.b64 %0,{%1,%2};":"=l"(r):"f"(lo),"f"(hi)); return r; }
static __device__ __forceinline__ void upk(ull v, float &lo, float &hi){ asm("mov.b64 {%0,%1},%2;":"=f"(lo),"=f"(hi):"l"(v)); }
static __device__ __forceinline__ void fma2(ull &d, ull a, ull b){ asm("fma.rn.f32x2 %0,%1,%2,%0;":"+l"(d):"l"(a),"l"(b)); }
static __device__ __forceinline__ float siluf(float z){ return z*(1.f/(1.f+__expf(-z))); }
static __device__ __forceinline__ float dsiluf(float z){ float s=1.f/(1.f+__expf(-z)); return s*(1.f+z*(1.f-s)); }

__device__ float g_cd[2][256];

// ---- SMEM float offsets ----
// BASE/TZ1: stride 34. A1/A2/TA2: stride 36. AT1 (interleaved p|t): stride 68, overlays A1+A2.
#define OFF_BASE 0            // 256*34 = 8704
#define OFF_TZ1  8704         // 256*34
#define OFF_A1   17408        // 256*36 = 9216
#define OFF_A2   26624        // 256*36
#define OFF_X    35840
#define OFF_FT   (OFF_X)          // 64*34 = 2176 (passes f,u,v)
#define OFF_S2F  (OFF_X+2176)     // k-split scratch (ull region, 4112 ull)
#define OFF_TA2  (OFF_X)          // 256*36 = 9216 (JVP passes; FT dead)
#define OFF_STF  (OFF_X+9216)     // tl3 scratch (JVP)
#define OFF_EPS  (OFF_X+13344)    // 64*34 = 2176
#define OFF_CU   51360            // 16*34
#define OFF_CV   51904
#define OFF_CF   52448
#define OFF_DR   52992            // 32
#define SMEM_FLOATS 53056

__global__ void precompute_k(const float* __restrict__ cu, const float* __restrict__ cv,
                             const float* __restrict__ W1){
    int c = threadIdx.x;
    float su = 0.f, sv = 0.f;
    #pragma unroll
    for (int j = 0; j < 16; j++){
        float w = __ldg(W1 + (65+j)*256 + c);
        su += __ldg(cu + j) * w;
        sv += __ldg(cv + j) * w;
    }
    g_cd[0][c] = su;
    g_cd[1][c] = sv;
}

__global__ void __launch_bounds__(TPB, 1) node_main(
    const float* __restrict__ gt, const float* __restrict__ gx, const float* __restrict__ geps,
    const float* __restrict__ gcu, const float* __restrict__ gcv, const float* __restrict__ gcf,
    const float* __restrict__ W1, const float* __restrict__ b1,
    const float* __restrict__ W2, const float* __restrict__ b2,
    const float* __restrict__ W3, const float* __restrict__ b3,
    float* __restrict__ out, int B)
{
    extern __shared__ float sm[];
    const int tid  = threadIdx.x;
    const int lane = tid & 31;
    const int row0 = blockIdx.x * 32;

    float* BASE = sm + OFF_BASE;
    float* TZ1  = sm + OFF_TZ1;
    float* A1   = sm + OFF_A1;    // stride 36
    float* A2   = sm + OFF_A2;    // stride 36
    float* AT1  = sm + OFF_A1;    // stride 68 interleaved (JVP), overlays A1+A2
    float* FT   = sm + OFF_FT;    // stride 34
    float* TA2  = sm + OFF_TA2;   // stride 36 (JVP)
    float* EPS  = sm + OFF_EPS;   // stride 34
    float* CUt  = sm + OFF_CU;
    float* CVt  = sm + OFF_CV;
    float* CFt  = sm + OFF_CF;
    float* DR   = sm + OFF_DR;
    float* YSH  = sm + OFF_A2;    // y tile overlay (dead before layer2s writes A2)
    ull*   S2   = (ull*)(sm + OFF_S2F);
    ull*   ST   = (ull*)(sm + OFF_STF);
    const ull ONE2 = pk(1.f, 1.f);

    // ---- thread mappings ----
    // base/fillA1/fillJ/layer2d (256 cols, no split): 64 cg x 8 rg, 4 cols x 4 rows
    const int c0A = 4*(tid & 63), r0A = 4*(tid >> 6);
    // k-split mappings (2 slices of 128 k)
    const int ks  = tid >> 8, t2 = tid & 255;
    const int kb  = ks * 128;
    // layer2s: 64 cg x 4 rg, 4 cols x 8 rows
    const int c0S = 4*(t2 & 63), r0S = 8*(t2 >> 6);
    // layer3: 32 cg x 8 rg, 4 cols x 4 rows (128 cols)
    const int c03 = 4*(t2 & 31), r03 = 4*((t2 >> 5) & 7);
    // tangent layer3: 32 cg x 8 rg, 2 cols x 4 rows (64 cols)
    const int c0T = 2*(t2 & 31), r0T = 4*((t2 >> 5) & 7);

    // ---- P0: tile loads (transposed) ----
    for (int i = tid; i < 64*32; i += TPB){
        int r = i & 31, d = i >> 5; int gr = row0 + r;
        YSH[d*34 + r] = (gr < B) ? gx[(size_t)gr*65 + d]  : 0.f;
        EPS[d*34 + r] = (gr < B) ? geps[(size_t)gr*64 + d] : 0.f;
    }
    for (int i = tid; i < 16*32; i += TPB){
        int r = i & 31, j = i >> 5; int gr = row0 + r; int gi = (gr < B) ? gr : 0;
        CUt[j*34 + r] = gcu[(size_t)gi*16 + j];
        CVt[j*34 + r] = gcv[(size_t)gi*16 + j];
        CFt[j*34 + r] = gcf[(size_t)gi*16 + j];
    }
    if (tid < 32) DR[tid] = 0.f;
    __syncthreads();

    // ---- P1: dual base GEMM: BASE = y@W1y + t*W1t + b1, TZ1 = e@W1y ----
    {
        ull aP[2][4], aT[2][4];
        #pragma unroll
        for (int i = 0; i < 2; i++)
            #pragma unroll
            for (int j = 0; j < 4; j++){ aP[i][j] = 0ULL; aT[i][j] = 0ULL; }
        #pragma unroll 4
        for (int k = 0; k < 64; k++){
            float4 w = __ldg(reinterpret_cast<const float4*>(W1 + k*256 + c0A));
            ull wv[4] = {pk(w.x,w.x), pk(w.y,w.y), pk(w.z,w.z), pk(w.w,w.w)};
            ull y0 = *reinterpret_cast<const ull*>(YSH + k*34 + r0A);
            ull y1 = *reinterpret_cast<const ull*>(YSH + k*34 + r0A + 2);
            ull e0 = *reinterpret_cast<const ull*>(EPS + k*34 + r0A);
            ull e1 = *reinterpret_cast<const ull*>(EPS + k*34 + r0A + 2);
            #pragma unroll
            for (int ci = 0; ci < 4; ci++){
                fma2(aP[0][ci], y0, wv[ci]); fma2(aP[1][ci], y1, wv[ci]);
                fma2(aT[0][ci], e0, wv[ci]); fma2(aT[1][ci], e1, wv[ci]);
            }
        }
        float tv = __ldg(gt);
        #pragma unroll
        for (int ci = 0; ci < 4; ci++){
            int c = c0A + ci;
            float s = tv*__ldg(W1 + 64*256 + c) + __ldg(b1 + c);
            #pragma unroll
            for (int rp = 0; rp < 2; rp++){
                float lo, hi;
                upk(aP[rp][ci], lo, hi);
                *reinterpret_cast<float2*>(BASE + c*34 + r0A + 2*rp) = make_float2(lo+s, hi+s);
                upk(aT[rp][ci], lo, hi);
                *reinterpret_cast<float2*>(TZ1 + c*34 + r0A + 2*rp) = make_float2(lo, hi);
            }
        }
    }
    __syncthreads();

    // ---- helpers ----
    auto fillA1 = [&](const float* ct){  // A1 = silu(BASE + cond@W1c)
        ull a[2][4];
        #pragma unroll
        for (int i = 0; i < 2; i++)
            #pragma unroll
            for (int j = 0; j < 4; j++) a[i][j] = 0ULL;
        #pragma unroll
        for (int k = 0; k < 16; k++){
            float4 w = __ldg(reinterpret_cast<const float4*>(W1 + (65+k)*256 + c0A));
            ull wv[4] = {pk(w.x,w.x), pk(w.y,w.y), pk(w.z,w.z), pk(w.w,w.w)};
            ull p0 = *reinterpret_cast<const ull*>(ct + k*34 + r0A);
            ull p1 = *reinterpret_cast<const ull*>(ct + k*34 + r0A + 2);
            #pragma unroll
            for (int ci = 0; ci < 4; ci++){ fma2(a[0][ci], p0, wv[ci]); fma2(a[1][ci], p1, wv[ci]); }
        }
        #pragma unroll
        for (int ci = 0; ci < 4; ci++){ int c = c0A + ci;
            #pragma unroll
            for (int rp = 0; rp < 2; rp++){
                float lo, hi; upk(a[rp][ci], lo, hi);
                float2 b = *reinterpret_cast<const float2*>(BASE + c*34 + r0A + 2*rp);
                *reinterpret_cast<float2*>(A1 + c*36 + r0A + 2*rp) =
                    make_float2(siluf(b.x + lo), siluf(b.y + hi));
            }
        }
    };

    auto layer2s = [&](){  // A2 = silu(A1@W2 + b2), 2-way k-split
        ull a[4][4];
        #pragma unroll
        for (int i = 0; i < 4; i++)
            #pragma unroll
            for (int j = 0; j < 4; j++) a[i][j] = 0ULL;
        #pragma unroll 4
        for (int kk = 0; kk < 128; kk++){
            int k = kb + kk;
            float4 w = __ldg(reinterpret_cast<const float4*>(W2 + k*256 + c0S));
            ull wv[4] = {pk(w.x,w.x), pk(w.y,w.y), pk(w.z,w.z), pk(w.w,w.w)};
            ulonglong2 p0 = *reinterpret_cast<const ulonglong2*>(A1 + k*36 + r0S);
            ulonglong2 p1 = *reinterpret_cast<const ulonglong2*>(A1 + k*36 + r0S + 4);
            #pragma unroll
            for (int ci = 0; ci < 4; ci++){
                fma2(a[0][ci], p0.x, wv[ci]); fma2(a[1][ci], p0.y, wv[ci]);
                fma2(a[2][ci], p1.x, wv[ci]); fma2(a[3][ci], p1.y, wv[ci]);
            }
        }
        if (ks == 1){
            #pragma unroll
            for (int j = 0; j < 16; j++) S2[j*257 + t2] = a[j>>2][j&3];
        }
        __syncthreads();
        if (ks == 0){
            #pragma unroll
            for (int j = 0; j < 16; j++) fma2(a[j>>2][j&3], S2[j*257 + t2], ONE2);
            #pragma unroll
            for (int ci = 0; ci < 4; ci++){ int c = c0S + ci; float bb = __ldg(b2 + c);
                #pragma unroll
                for (int rp = 0; rp < 4; rp++){
                    float lo, hi; upk(a[rp][ci], lo, hi);
                    *reinterpret_cast<float2*>(A2 + c*36 + r0S + 2*rp) =
                        make_float2(siluf(lo + bb), siluf(hi + bb));
                }
            }
        }
    };

    // layer3: mode 0 = f (stage FT + write ft), else corr-reduce with sign sgn
    auto layer3 = [&](int mode, float sgn){
        ull a[2][4];
        #pragma unroll
        for (int i = 0; i < 2; i++)
            #pragma unroll
            for (int j = 0; j < 4; j++) a[i][j] = 0ULL;
        #pragma unroll 4
        for (int kk = 0; kk < 128; kk++){
            int k = kb + kk;
            float4 w = __ldg(reinterpret_cast<const float4*>(W3 + k*128 + c03));
            ull wv[4] = {pk(w.x,w.x), pk(w.y,w.y), pk(w.z,w.z), pk(w.w,w.w)};
            ulonglong2 p = *reinterpret_cast<const ulonglong2*>(A2 + k*36 + r03);
            #pragma unroll
            for (int ci = 0; ci < 4; ci++){ fma2(a[0][ci], p.x, wv[ci]); fma2(a[1][ci], p.y, wv[ci]); }
        }
        if (ks == 1){
            #pragma unroll
            for (int j = 0; j < 8; j++) S2[j*257 + t2] = a[j>>2][j&3];
        }
        __syncthreads();
        if (ks == 0){
            #pragma unroll
            for (int j = 0; j < 8; j++) fma2(a[j>>2][j&3], S2[j*257 + t2], ONE2);
            // add bias
            #pragma unroll
            for (int ci = 0; ci < 4; ci++){ int c = c03 + ci; float bb = __ldg(b3 + c);
                ull b2v = pk(bb, bb);
                fma2(a[0][ci], ONE2, b2v);
                fma2(a[1][ci], ONE2, b2v);
            }
            if (mode == 0){
                if (c03 < 64){
                    #pragma unroll
                    for (int ci = 0; ci < 4; ci++){ int c = c03 + ci;
                        #pragma unroll
                        for (int rp = 0; rp < 2; rp++){
                            float lo, hi; upk(a[rp][ci], lo, hi);
                            *reinterpret_cast<float2*>(FT + c*34 + r03 + 2*rp) = make_float2(lo, hi);
                            int gr = row0 + r03 + 2*rp;
                            if (gr   < B) out[(size_t)gr*65 + c]     = lo;
                            if (gr+1 < B) out[(size_t)(gr+1)*65 + c] = hi;
                        }
                    }
                }
            } else {
                // fetch score (cols 64+c) from lane+16; lanes<16 hold ut
                ull sc[2][4];
                #pragma unroll
                for (int rp = 0; rp < 2; rp++)
                    #pragma unroll
                    for (int ci = 0; ci < 4; ci++)
                        sc[rp][ci] = __shfl_sync(0xffffffffu, a[rp][ci], lane + 16);
                float part[4] = {0.f, 0.f, 0.f, 0.f};
                if (lane < 16){
                    #pragma unroll
                    for (int ci = 0; ci < 4; ci++){ int c = c03 + ci;
                        #pragma unroll
                        for (int rp = 0; rp < 2; rp++){
                            float u0, u1, s0, s1;
                            upk(a[rp][ci], u0, u1); upk(sc[rp][ci], s0, s1);
                            float f0 = FT[c*34 + r03 + 2*rp];
                            float f1 = FT[c*34 + r03 + 2*rp + 1];
                            part[2*rp]   += (f0 - u0) * s0;
                            part[2*rp+1] += (f1 - u1) * s1;
                        }
                    }
                }
                #pragma unroll
                for (int off = 8; off >= 1; off >>= 1){
                    #pragma unroll
                    for (int i = 0; i < 4; i++)
                        part[i] += __shfl_down_sync(0xffffffffu, part[i], off, 16);
                }
                if (lane == 0){
                    #pragma unroll
                    for (int i = 0; i < 4; i++) DR[r03 + i] += sgn * part[i];
                }
            }
        }
    };

    auto fillJ = [&](int uv){  // AT1 interleaved: [p0 p1 t0 t1] per row-pair
        #pragma unroll
        for (int ci = 0; ci < 4; ci++){ int c = c0A + ci;
            float cd = g_cd[uv][c];
            #pragma unroll
            for (int rp = 0; rp < 2; rp++){
                float2 b  = *reinterpret_cast<const float2*>(BASE + c*34 + r0A + 2*rp);
                float2 tz = *reinterpret_cast<const float2*>(TZ1  + c*34 + r0A + 2*rp);
                float z0 = b.x + cd, z1 = b.y + cd;
                float4 v = make_float4(siluf(z0), siluf(z1), dsiluf(z0)*tz.x, dsiluf(z1)*tz.y);
                *reinterpret_cast<float4*>(AT1 + c*68 + 2*r0A + 4*rp) = v;
            }
        }
    };

    auto layer2d = [&](){  // TA2 = silu'(z2) * (ta1@W2), z2 from primal; only tangent stored
        ull aP[2][4], aT[2][4];
        #pragma unroll
        for (int i = 0; i < 2; i++)
            #pragma unroll
            for (int j = 0; j < 4; j++){ aP[i][j] = 0ULL; aT[i][j] = 0ULL; }
        #pragma unroll 4
        for (int k = 0; k < 256; k++){
            float4 w = __ldg(reinterpret_cast<const float4*>(W2 + k*256 + c0A));
            ull wv[4] = {pk(w.x,w.x), pk(w.y,w.y), pk(w.z,w.z), pk(w.w,w.w)};
            ulonglong2 q0 = *reinterpret_cast<const ulonglong2*>(AT1 + k*68 + 2*r0A);
            ulonglong2 q1 = *reinterpret_cast<const ulonglong2*>(AT1 + k*68 + 2*r0A + 4);
            #pragma unroll
            for (int ci = 0; ci < 4; ci++){
                fma2(aP[0][ci], q0.x, wv[ci]); fma2(aT[0][ci], q0.y, wv[ci]);
                fma2(aP[1][ci], q1.x, wv[ci]); fma2(aT[1][ci], q1.y, wv[ci]);
            }
        }
        #pragma unroll
        for (int ci = 0; ci < 4; ci++){ int c = c0A + ci; float bb = __ldg(b2 + c);
            #pragma unroll
            for (int rp = 0; rp < 2; rp++){
                float z0, z1, t0, t1;
                upk(aP[rp][ci], z0, z1); upk(aT[rp][ci], t0, t1);
                z0 += bb; z1 += bb;
                *reinterpret_cast<float2*>(TA2 + c*36 + r0A + 2*rp) =
                    make_float2(dsiluf(z0)*t0, dsiluf(z1)*t1);
            }
        }
    };

    auto tl3 = [&](float sgn){  // div partials: sum_c (TA2@W3[:, :64])[c,r] * eps[c,r]
        ull a[2][2];
        #pragma unroll
        for (int i = 0; i < 2; i++){ a[i][0] = 0ULL; a[i][1] = 0ULL; }
        #pragma unroll 4
        for (int kk = 0; kk < 128; kk++){
            int k = kb + kk;
            float2 w = __ldg(reinterpret_cast<const float2*>(W3 + k*128 + c0T));
            ull wv[2] = {pk(w.x,w.x), pk(w.y,w.y)};
            ulonglong2 p = *reinterpret_cast<const ulonglong2*>(TA2 + k*36 + r0T);
            #pragma unroll
            for (int ci = 0; ci < 2; ci++){ fma2(a[0][ci], p.x, wv[ci]); fma2(a[1][ci], p.y, wv[ci]); }
        }
        if (ks == 1){
            #pragma unroll
            for (int j = 0; j < 4; j++) ST[j*257 + t2] = a[j>>1][j&1];
        }
        __syncthreads();
        if (ks == 0){
            #pragma unroll
            for (int j = 0; j < 4; j++) fma2(a[j>>1][j&1], ST[j*257 + t2], ONE2);
            float part[4] = {0.f, 0.f, 0.f, 0.f};
            #pragma unroll
            for (int ci = 0; ci < 2; ci++){ int c = c0T + ci;
                #pragma unroll
                for (int rp = 0; rp < 2; rp++){
                    float v0, v1; upk(a[rp][ci], v0, v1);
                    part[2*rp]   += v0 * EPS[c*34 + r0T + 2*rp];
                    part[2*rp+1] += v1 * EPS[c*34 + r0T + 2*rp + 1];
                }
            }
            #pragma unroll
            for (int off = 16; off >= 1; off >>= 1){
                #pragma unroll
                for (int i = 0; i < 4; i++)
                    part[i] += __shfl_down_sync(0xffffffffu, part[i], off, 32);
            }
            if (lane == 0){
                #pragma unroll
                for (int i = 0; i < 4; i++) DR[r0T + i] += sgn * part[i];
            }
        }
    };

    // ---- pass f ----
    fillA1(CFt); __syncthreads();
    layer2s();   __syncthreads();
    layer3(0, 0.f); __syncthreads();

    // ---- pass u: corr_u = sum (ft-ut)*score_u ----
    fillA1(CUt); __syncthreads();
    layer2s();   __syncthreads();
    layer3(1, 1.f); __syncthreads();

    // ---- pass v: corr_v = -sum (ft-vt)*score_v ----
    fillA1(CVt); __syncthreads();
    layer2s();   __syncthreads();
    layer3(2, -1.f); __syncthreads();

    // ---- JVP u: div -= e.(Ju e) ----
    fillJ(0);  __syncthreads();
    layer2d(); __syncthreads();
    tl3(-1.f); __syncthreads();

    // ---- JVP v: div += e.(Jv e) ----
    fillJ(1);  __syncthreads();
    layer2d(); __syncthreads();
    tl3(1.f);  __syncthreads();

    // ---- write dr ----
    if (tid < 32){
        int gr = row0 + tid;
        if (gr < B) out[(size_t)gr*65 + 64] = DR[tid];
    }
}

extern "C" void kernel_launch(void* const* d_in, const int* in_sizes, int n_in,
                              void* d_out, int out_size)
{
    const float* gt  = (const float*)d_in[0];
    const float* gx  = (const float*)d_in[1];
    const float* ge  = (const float*)d_in[2];
    const float* gcu = (const float*)d_in[3];
    const float* gcv = (const float*)d_in[4];
    const float* gcf = (const float*)d_in[5];
    const float* W1  = (const float*)d_in[6];
    const float* b1  = (const float*)d_in[7];
    const float* W2  = (const float*)d_in[8];
    const float* b2  = (const float*)d_in[9];
    const float* W3  = (const float*)d_in[10];
    const float* b3  = (const float*)d_in[11];
    float* out = (float*)d_out;

    int B = in_sizes[1] / 65;
    int grid = (B + 31) / 32;

    cudaFuncSetAttribute(node_main, cudaFuncAttributeMaxDynamicSharedMemorySize, SMEM_FLOATS*4);

    precompute_k<<<1, 256>>>(gcu, gcv, W1);
    node_main<<<grid, TPB, SMEM_FLOATS*4>>>(gt, gx, ge, gcu, gcv, gcf,
                                            W1, b1, W2, b2, W3, b3, out, B);
}

// round 6
// speedup vs baseline: 1.4055x; 1.0001x over previous
#include <cuda_runtime.h>

#define TPB 512

typedef unsigned long long ull;

static __device__ __forceinline__ ull pk(float lo, float hi){ ull r; asm("mov.b64 %0,{%1,%2};":"=l"(r):"f"(lo),"f"(hi)); return r; }
static __device__ __forceinline__ void upk(ull v, float &lo, float &hi){ asm("mov.b64 {%0,%1},%2;":"=f"(lo),"=f"(hi):"l"(v)); }
static __device__ __forceinline__ void fma2(ull &d, ull a, ull b){ asm("fma.rn.f32x2 %0,%1,%2,%0;":"+l"(d):"l"(a),"l"(b)); }
static __device__ __forceinline__ float siluf(float z){ return z*(1.f/(1.f+__expf(-z))); }
static __device__ __forceinline__ float dsiluf(float z){ float s=1.f/(1.f+__expf(-z)); return s*(1.f+z*(1.f-s)); }

__device__ float g_cd[2][256];

// ---- SMEM float offsets ----
// BASE/TZ1: stride 34. A1/A2/TA2: stride 36. AT1 (interleaved p|t): stride 68, overlays A1+A2.
#define OFF_BASE 0            // 256*34 = 8704
#define OFF_TZ1  8704         // 256*34
#define OFF_A1   17408        // 256*36 = 9216
#define OFF_A2   26624        // 256*36
#define OFF_X    35840
#define OFF_FT   (OFF_X)          // 64*34 = 2176 (passes f,u,v)
#define OFF_S2F  (OFF_X+2176)     // k-split scratch (ull region, 4112 ull)
#define OFF_TA2  (OFF_X)          // 256*36 = 9216 (JVP passes; FT dead)
#define OFF_STF  (OFF_X+9216)     // tl3 scratch (JVP)
#define OFF_EPS  (OFF_X+13344)    // 64*34 = 2176
#define OFF_CU   51360            // 16*34
#define OFF_CV   51904
#define OFF_CF   52448
#define OFF_DR   52992            // 32
#define SMEM_FLOATS 53056

__global__ void precompute_k(const float* __restrict__ cu, const float* __restrict__ cv,
                             const float* __restrict__ W1){
    int c = threadIdx.x;
    float su = 0.f, sv = 0.f;
    #pragma unroll
    for (int j = 0; j < 16; j++){
        float w = __ldg(W1 + (65+j)*256 + c);
        su += __ldg(cu + j) * w;
        sv += __ldg(cv + j) * w;
    }
    g_cd[0][c] = su;
    g_cd[1][c] = sv;
}

__global__ void __launch_bounds__(TPB, 1) node_main(
    const float* __restrict__ gt, const float* __restrict__ gx, const float* __restrict__ geps,
    const float* __restrict__ gcu, const float* __restrict__ gcv, const float* __restrict__ gcf,
    const float* __restrict__ W1, const float* __restrict__ b1,
    const float* __restrict__ W2, const float* __restrict__ b2,
    const float* __restrict__ W3, const float* __restrict__ b3,
    float* __restrict__ out, int B)
{
    extern __shared__ float sm[];
    const int tid  = threadIdx.x;
    const int lane = tid & 31;
    const int row0 = blockIdx.x * 32;

    float* BASE = sm + OFF_BASE;
    float* TZ1  = sm + OFF_TZ1;
    float* A1   = sm + OFF_A1;    // stride 36
    float* A2   = sm + OFF_A2;    // stride 36
    float* AT1  = sm + OFF_A1;    // stride 68 interleaved (JVP), overlays A1+A2
    float* FT   = sm + OFF_FT;    // stride 34
    float* TA2  = sm + OFF_TA2;   // stride 36 (JVP)
    float* EPS  = sm + OFF_EPS;   // stride 34
    float* CUt  = sm + OFF_CU;
    float* CVt  = sm + OFF_CV;
    float* CFt  = sm + OFF_CF;
    float* DR   = sm + OFF_DR;
    float* YSH  = sm + OFF_A2;    // y tile overlay (dead before layer2s writes A2)
    ull*   S2   = (ull*)(sm + OFF_S2F);
    ull*   ST   = (ull*)(sm + OFF_STF);
    const ull ONE2 = pk(1.f, 1.f);

    // ---- thread mappings ----
    // base/fillA1/fillJ/layer2d (256 cols, no split): 64 cg x 8 rg, 4 cols x 4 rows
    const int c0A = 4*(tid & 63), r0A = 4*(tid >> 6);
    // k-split mappings (2 slices of 128 k)
    const int ks  = tid >> 8, t2 = tid & 255;
    const int kb  = ks * 128;
    // layer2s: 64 cg x 4 rg, 4 cols x 8 rows
    const int c0S = 4*(t2 & 63), r0S = 8*(t2 >> 6);
    // layer3: 32 cg x 8 rg, 4 cols x 4 rows (128 cols)
    const int c03 = 4*(t2 & 31), r03 = 4*((t2 >> 5) & 7);
    // tangent layer3: 32 cg x 8 rg, 2 cols x 4 rows (64 cols)
    const int c0T = 2*(t2 & 31), r0T = 4*((t2 >> 5) & 7);

    // ---- P0: tile loads (transposed) ----
    for (int i = tid; i < 64*32; i += TPB){
        int r = i & 31, d = i >> 5; int gr = row0 + r;
        YSH[d*34 + r] = (gr < B) ? gx[(size_t)gr*65 + d]  : 0.f;
        EPS[d*34 + r] = (gr < B) ? geps[(size_t)gr*64 + d] : 0.f;
    }
    for (int i = tid; i < 16*32; i += TPB){
        int r = i & 31, j = i >> 5; int gr = row0 + r; int gi = (gr < B) ? gr : 0;
        CUt[j*34 + r] = gcu[(size_t)gi*16 + j];
        CVt[j*34 + r] = gcv[(size_t)gi*16 + j];
        CFt[j*34 + r] = gcf[(size_t)gi*16 + j];
    }
    if (tid < 32) DR[tid] = 0.f;
    __syncthreads();

    // ---- P1: dual base GEMM: BASE = y@W1y + t*W1t + b1, TZ1 = e@W1y ----
    {
        ull aP[2][4], aT[2][4];
        #pragma unroll
        for (int i = 0; i < 2; i++)
            #pragma unroll
            for (int j = 0; j < 4; j++){ aP[i][j] = 0ULL; aT[i][j] = 0ULL; }
        #pragma unroll 4
        for (int k = 0; k < 64; k++){
            float4 w = __ldg(reinterpret_cast<const float4*>(W1 + k*256 + c0A));
            ull wv[4] = {pk(w.x,w.x), pk(w.y,w.y), pk(w.z,w.z), pk(w.w,w.w)};
            ull y0 = *reinterpret_cast<const ull*>(YSH + k*34 + r0A);
            ull y1 = *reinterpret_cast<const ull*>(YSH + k*34 + r0A + 2);
            ull e0 = *reinterpret_cast<const ull*>(EPS + k*34 + r0A);
            ull e1 = *reinterpret_cast<const ull*>(EPS + k*34 + r0A + 2);
            #pragma unroll
            for (int ci = 0; ci < 4; ci++){
                fma2(aP[0][ci], y0, wv[ci]); fma2(aP[1][ci], y1, wv[ci]);
                fma2(aT[0][ci], e0, wv[ci]); fma2(aT[1][ci], e1, wv[ci]);
            }
        }
        float tv = __ldg(gt);
        #pragma unroll
        for (int ci = 0; ci < 4; ci++){
            int c = c0A + ci;
            float s = tv*__ldg(W1 + 64*256 + c) + __ldg(b1 + c);
            #pragma unroll
            for (int rp = 0; rp < 2; rp++){
                float lo, hi;
                upk(aP[rp][ci], lo, hi);
                *reinterpret_cast<float2*>(BASE + c*34 + r0A + 2*rp) = make_float2(lo+s, hi+s);
                upk(aT[rp][ci], lo, hi);
                *reinterpret_cast<float2*>(TZ1 + c*34 + r0A + 2*rp) = make_float2(lo, hi);
            }
        }
    }
    __syncthreads();

    // ---- helpers ----
    auto fillA1 = [&](const float* ct){  // A1 = silu(BASE + cond@W1c)
        ull a[2][4];
        #pragma unroll
        for (int i = 0; i < 2; i++)
            #pragma unroll
            for (int j = 0; j < 4; j++) a[i][j] = 0ULL;
        #pragma unroll
        for (int k = 0; k < 16; k++){
            float4 w = __ldg(reinterpret_cast<const float4*>(W1 + (65+k)*256 + c0A));
            ull wv[4] = {pk(w.x,w.x), pk(w.y,w.y), pk(w.z,w.z), pk(w.w,w.w)};
            ull p0 = *reinterpret_cast<const ull*>(ct + k*34 + r0A);
            ull p1 = *reinterpret_cast<const ull*>(ct + k*34 + r0A + 2);
            #pragma unroll
            for (int ci = 0; ci < 4; ci++){ fma2(a[0][ci], p0, wv[ci]); fma2(a[1][ci], p1, wv[ci]); }
        }
        #pragma unroll
        for (int ci = 0; ci < 4; ci++){ int c = c0A + ci;
            #pragma unroll
            for (int rp = 0; rp < 2; rp++){
                float lo, hi; upk(a[rp][ci], lo, hi);
                float2 b = *reinterpret_cast<const float2*>(BASE + c*34 + r0A + 2*rp);
                *reinterpret_cast<float2*>(A1 + c*36 + r0A + 2*rp) =
                    make_float2(siluf(b.x + lo), siluf(b.y + hi));
            }
        }
    };

    auto layer2s = [&](){  // A2 = silu(A1@W2 + b2), 2-way k-split
        ull a[4][4];
        #pragma unroll
        for (int i = 0; i < 4; i++)
            #pragma unroll
            for (int j = 0; j < 4; j++) a[i][j] = 0ULL;
        #pragma unroll 4
        for (int kk = 0; kk < 128; kk++){
            int k = kb + kk;
            float4 w = __ldg(reinterpret_cast<const float4*>(W2 + k*256 + c0S));
            ull wv[4] = {pk(w.x,w.x), pk(w.y,w.y), pk(w.z,w.z), pk(w.w,w.w)};
            ulonglong2 p0 = *reinterpret_cast<const ulonglong2*>(A1 + k*36 + r0S);
            ulonglong2 p1 = *reinterpret_cast<const ulonglong2*>(A1 + k*36 + r0S + 4);
            #pragma unroll
            for (int ci = 0; ci < 4; ci++){
                fma2(a[0][ci], p0.x, wv[ci]); fma2(a[1][ci], p0.y, wv[ci]);
                fma2(a[2][ci], p1.x, wv[ci]); fma2(a[3][ci], p1.y, wv[ci]);
            }
        }
        if (ks == 1){
            #pragma unroll
            for (int j = 0; j < 16; j++) S2[j*257 + t2] = a[j>>2][j&3];
        }
        __syncthreads();
        if (ks == 0){
            #pragma unroll
            for (int j = 0; j < 16; j++) fma2(a[j>>2][j&3], S2[j*257 + t2], ONE2);
            #pragma unroll
            for (int ci = 0; ci < 4; ci++){ int c = c0S + ci; float bb = __ldg(b2 + c);
                #pragma unroll
                for (int rp = 0; rp < 4; rp++){
                    float lo, hi; upk(a[rp][ci], lo, hi);
                    *reinterpret_cast<float2*>(A2 + c*36 + r0S + 2*rp) =
                        make_float2(siluf(lo + bb), siluf(hi + bb));
                }
            }
        }
    };

    // layer3: mode 0 = f (stage FT + write ft), else corr-reduce with sign sgn
    auto layer3 = [&](int mode, float sgn){
        ull a[2][4];
        #pragma unroll
        for (int i = 0; i < 2; i++)
            #pragma unroll
            for (int j = 0; j < 4; j++) a[i][j] = 0ULL;
        #pragma unroll 4
        for (int kk = 0; kk < 128; kk++){
            int k = kb + kk;
            float4 w = __ldg(reinterpret_cast<const float4*>(W3 + k*128 + c03));
            ull wv[4] = {pk(w.x,w.x), pk(w.y,w.y), pk(w.z,w.z), pk(w.w,w.w)};
            ulonglong2 p = *reinterpret_cast<const ulonglong2*>(A2 + k*36 + r03);
            #pragma unroll
            for (int ci = 0; ci < 4; ci++){ fma2(a[0][ci], p.x, wv[ci]); fma2(a[1][ci], p.y, wv[ci]); }
        }
        if (ks == 1){
            #pragma unroll
            for (int j = 0; j < 8; j++) S2[j*257 + t2] = a[j>>2][j&3];
        }
        __syncthreads();
        if (ks == 0){
            #pragma unroll
            for (int j = 0; j < 8; j++) fma2(a[j>>2][j&3], S2[j*257 + t2], ONE2);
            // add bias
            #pragma unroll
            for (int ci = 0; ci < 4; ci++){ int c = c03 + ci; float bb = __ldg(b3 + c);
                ull b2v = pk(bb, bb);
                fma2(a[0][ci], ONE2, b2v);
                fma2(a[1][ci], ONE2, b2v);
            }
            if (mode == 0){
                if (c03 < 64){
                    #pragma unroll
                    for (int ci = 0; ci < 4; ci++){ int c = c03 + ci;
                        #pragma unroll
                        for (int rp = 0; rp < 2; rp++){
                            float lo, hi; upk(a[rp][ci], lo, hi);
                            *reinterpret_cast<float2*>(FT + c*34 + r03 + 2*rp) = make_float2(lo, hi);
                            int gr = row0 + r03 + 2*rp;
                            if (gr   < B) out[(size_t)gr*65 + c]     = lo;
                            if (gr+1 < B) out[(size_t)(gr+1)*65 + c] = hi;
                        }
                    }
                }
            } else {
                // fetch score (cols 64+c) from lane+16; lanes<16 hold ut
                ull sc[2][4];
                #pragma unroll
                for (int rp = 0; rp < 2; rp++)
                    #pragma unroll
                    for (int ci = 0; ci < 4; ci++)
                        sc[rp][ci] = __shfl_sync(0xffffffffu, a[rp][ci], lane + 16);
                float part[4] = {0.f, 0.f, 0.f, 0.f};
                if (lane < 16){
                    #pragma unroll
                    for (int ci = 0; ci < 4; ci++){ int c = c03 + ci;
                        #pragma unroll
                        for (int rp = 0; rp < 2; rp++){
                            float u0, u1, s0, s1;
                            upk(a[rp][ci], u0, u1); upk(sc[rp][ci], s0, s1);
                            float f0 = FT[c*34 + r03 + 2*rp];
                            float f1 = FT[c*34 + r03 + 2*rp + 1];
                            part[2*rp]   += (f0 - u0) * s0;
                            part[2*rp+1] += (f1 - u1) * s1;
                        }
                    }
                }
                #pragma unroll
                for (int off = 8; off >= 1; off >>= 1){
                    #pragma unroll
                    for (int i = 0; i < 4; i++)
                        part[i] += __shfl_down_sync(0xffffffffu, part[i], off, 16);
                }
                if (lane == 0){
                    #pragma unroll
                    for (int i = 0; i < 4; i++) DR[r03 + i] += sgn * part[i];
                }
            }
        }
    };

    auto fillJ = [&](int uv){  // AT1 interleaved: [p0 p1 t0 t1] per row-pair
        #pragma unroll
        for (int ci = 0; ci < 4; ci++){ int c = c0A + ci;
            float cd = g_cd[uv][c];
            #pragma unroll
            for (int rp = 0; rp < 2; rp++){
                float2 b  = *reinterpret_cast<const float2*>(BASE + c*34 + r0A + 2*rp);
                float2 tz = *reinterpret_cast<const float2*>(TZ1  + c*34 + r0A + 2*rp);
                float z0 = b.x + cd, z1 = b.y + cd;
                float4 v = make_float4(siluf(z0), siluf(z1), dsiluf(z0)*tz.x, dsiluf(z1)*tz.y);
                *reinterpret_cast<float4*>(AT1 + c*68 + 2*r0A + 4*rp) = v;
            }
        }
    };

    auto layer2d = [&](){  // TA2 = silu'(z2) * (ta1@W2), z2 from primal; only tangent stored
        ull aP[2][4], aT[2][4];
        #pragma unroll
        for (int i = 0; i < 2; i++)
            #pragma unroll
            for (int j = 0; j < 4; j++){ aP[i][j] = 0ULL; aT[i][j] = 0ULL; }
        #pragma unroll 4
        for (int k = 0; k < 256; k++){
            float4 w = __ldg(reinterpret_cast<const float4*>(W2 + k*256 + c0A));
            ull wv[4] = {pk(w.x,w.x), pk(w.y,w.y), pk(w.z,w.z), pk(w.w,w.w)};
            ulonglong2 q0 = *reinterpret_cast<const ulonglong2*>(AT1 + k*68 + 2*r0A);
            ulonglong2 q1 = *reinterpret_cast<const ulonglong2*>(AT1 + k*68 + 2*r0A + 4);
            #pragma unroll
            for (int ci = 0; ci < 4; ci++){
                fma2(aP[0][ci], q0.x, wv[ci]); fma2(aT[0][ci], q0.y, wv[ci]);
                fma2(aP[1][ci], q1.x, wv[ci]); fma2(aT[1][ci], q1.y, wv[ci]);
            }
        }
        #pragma unroll
        for (int ci = 0; ci < 4; ci++){ int c = c0A + ci; float bb = __ldg(b2 + c);
            #pragma unroll
            for (int rp = 0; rp < 2; rp++){
                float z0, z1, t0, t1;
                upk(aP[rp][ci], z0, z1); upk(aT[rp][ci], t0, t1);
                z0 += bb; z1 += bb;
                *reinterpret_cast<float2*>(TA2 + c*36 + r0A + 2*rp) =
                    make_float2(dsiluf(z0)*t0, dsiluf(z1)*t1);
            }
        }
    };

    auto tl3 = [&](float sgn){  // div partials: sum_c (TA2@W3[:, :64])[c,r] * eps[c,r]
        ull a[2][2];
        #pragma unroll
        for (int i = 0; i < 2; i++){ a[i][0] = 0ULL; a[i][1] = 0ULL; }
        #pragma unroll 4
        for (int kk = 0; kk < 128; kk++){
            int k = kb + kk;
            float2 w = __ldg(reinterpret_cast<const float2*>(W3 + k*128 + c0T));
            ull wv[2] = {pk(w.x,w.x), pk(w.y,w.y)};
            ulonglong2 p = *reinterpret_cast<const ulonglong2*>(TA2 + k*36 + r0T);
            #pragma unroll
            for (int ci = 0; ci < 2; ci++){ fma2(a[0][ci], p.x, wv[ci]); fma2(a[1][ci], p.y, wv[ci]); }
        }
        if (ks == 1){
            #pragma unroll
            for (int j = 0; j < 4; j++) ST[j*257 + t2] = a[j>>1][j&1];
        }
        __syncthreads();
        if (ks == 0){
            #pragma unroll
            for (int j = 0; j < 4; j++) fma2(a[j>>1][j&1], ST[j*257 + t2], ONE2);
            float part[4] = {0.f, 0.f, 0.f, 0.f};
            #pragma unroll
            for (int ci = 0; ci < 2; ci++){ int c = c0T + ci;
                #pragma unroll
                for (int rp = 0; rp < 2; rp++){
                    float v0, v1; upk(a[rp][ci], v0, v1);
                    part[2*rp]   += v0 * EPS[c*34 + r0T + 2*rp];
                    part[2*rp+1] += v1 * EPS[c*34 + r0T + 2*rp + 1];
                }
            }
            #pragma unroll
            for (int off = 16; off >= 1; off >>= 1){
                #pragma unroll
                for (int i = 0; i < 4; i++)
                    part[i] += __shfl_down_sync(0xffffffffu, part[i], off, 32);
            }
            if (lane == 0){
                #pragma unroll
                for (int i = 0; i < 4; i++) DR[r0T + i] += sgn * part[i];
            }
        }
    };

    // ---- pass f ----
    fillA1(CFt); __syncthreads();
    layer2s();   __syncthreads();
    layer3(0, 0.f); __syncthreads();

    // ---- pass u: corr_u = sum (ft-ut)*score_u ----
    fillA1(CUt); __syncthreads();
    layer2s();   __syncthreads();
    layer3(1, 1.f); __syncthreads();

    // ---- pass v: corr_v = -sum (ft-vt)*score_v ----
    fillA1(CVt); __syncthreads();
    layer2s();   __syncthreads();
    layer3(2, -1.f); __syncthreads();

    // ---- JVP u: div -= e.(Ju e) ----
    fillJ(0);  __syncthreads();
    layer2d(); __syncthreads();
    tl3(-1.f); __syncthreads();

    // ---- JVP v: div += e.(Jv e) ----
    fillJ(1);  __syncthreads();
    layer2d(); __syncthreads();
    tl3(1.f);  __syncthreads();

    // ---- write dr ----
    if (tid < 32){
        int gr = row0 + tid;
        if (gr < B) out[(size_t)gr*65 + 64] = DR[tid];
    }
}

extern "C" void kernel_launch(void* const* d_in, const int* in_sizes, int n_in,
                              void* d_out, int out_size)
{
    const float* gt  = (const float*)d_in[0];
    const float* gx  = (const float*)d_in[1];
    const float* ge  = (const float*)d_in[2];
    const float* gcu = (const float*)d_in[3];
    const float* gcv = (const float*)d_in[4];
    const float* gcf = (const float*)d_in[5];
    const float* W1  = (const float*)d_in[6];
    const float* b1  = (const float*)d_in[7];
    const float* W2  = (const float*)d_in[8];
    const float* b2  = (const float*)d_in[9];
    const float* W3  = (const float*)d_in[10];
    const float* b3  = (const float*)d_in[11];
    float* out = (float*)d_out;

    int B = in_sizes[1] / 65;
    int grid = (B + 31) / 32;

    cudaFuncSetAttribute(node_main, cudaFuncAttributeMaxDynamicSharedMemorySize, SMEM_FLOATS*4);

    precompute_k<<<1, 256>>>(gcu, gcv, W1);
    node_main<<<grid, TPB, SMEM_FLOATS*4>>>(gt, gx, ge, gcu, gcv, gcf,
                                            W1, b1, W2, b2, W3, b3, out, B);
}